// round 6
// baseline (speedup 1.0000x reference)
#include <cuda_runtime.h>
#include <cstdint>

// Masked LeNet-C3 conv on GB300 (sm_103, no tcgen05 available in harness PTX target).
// x: [64,6,512,512] f32, W: [16,6,5,5] f32, b: [16] f32 -> out: [64,16,508,508] f32 (VALID 5x5)
// Round 6: 384-thread blocks, 2 CTAs/SM (24 warps, 6/SMSP) to break the issue/latency bound.

#define NIC 6
#define NOC 16
#define IH 512
#define IW 512
#define OH 508
#define OW 508
#define TILE_W 64
#define TILE_H 24
#define RPT 2            // output rows per thread (12 warps x 2 = 24 rows)
#define IN_ROWS 28       // TILE_H + 4
#define IN_WS 72         // interleaved: slot 2c -> col c (c<36), slot 2c+1 -> col c+32 (c<36)
#define NTHREADS 384
#define NACT 10          // active output channels per input channel

typedef unsigned long long ull;

// Active oc list per ic (LeNet-5 C3 table). constexpr FUNCTION so device code
// folds it at compile time without --expt-relaxed-constexpr.
__host__ __device__ constexpr int active(int ic, int slot) {
    constexpr int A[NIC][NACT] = {
        {0, 4, 5, 6, 9, 10, 11, 12, 14, 15},
        {0, 1, 5, 6, 7, 10, 11, 12, 13, 15},
        {0, 1, 2, 6, 7, 8, 11, 13, 14, 15},
        {1, 2, 3, 6, 7, 8, 9, 12, 14, 15},
        {2, 3, 4, 7, 8, 9, 10, 12, 13, 15},
        {3, 4, 5, 8, 9, 10, 11, 13, 14, 15},
    };
    return A[ic][slot];
}

__device__ __forceinline__ void fma2(ull& acc, ull a, ull w) {
    asm("fma.rn.f32x2 %0, %1, %2, %0;" : "+l"(acc) : "l"(a), "l"(w));
}

template<int IC>
__device__ __forceinline__ void conv_ic(const float* __restrict__ s_in,
                                        const float* __restrict__ s_w,
                                        ull acc[RPT][NOC],
                                        int row0, int tx)
{
    const float* in_ic = s_in + IC * IN_ROWS * IN_WS;
    #pragma unroll 1
    for (int ky = 0; ky < 5; ky++) {
        #pragma unroll
        for (int kx = 0; kx < 5; kx++) {
            const int k = ky * 5 + kx;
            const ulonglong2* wp = reinterpret_cast<const ulonglong2*>(
                s_w + (IC * 25 + k) * (2 * NACT));
            // x pixel pairs for both rows (LDS.64 each)
            ull xv0 = *reinterpret_cast<const ull*>(
                in_ic + (row0 + 0 + ky) * IN_WS + 2 * (tx + kx));
            ull xv1 = *reinterpret_cast<const ull*>(
                in_ic + (row0 + 1 + ky) * IN_WS + 2 * (tx + kx));
            // interleave weight loads with FMAs to keep transient regs low
            {
                ulonglong2 w01 = wp[0];
                fma2(acc[0][active(IC, 0)], xv0, w01.x);
                fma2(acc[1][active(IC, 0)], xv1, w01.x);
                fma2(acc[0][active(IC, 1)], xv0, w01.y);
                fma2(acc[1][active(IC, 1)], xv1, w01.y);
            }
            {
                ulonglong2 w23 = wp[1];
                fma2(acc[0][active(IC, 2)], xv0, w23.x);
                fma2(acc[1][active(IC, 2)], xv1, w23.x);
                fma2(acc[0][active(IC, 3)], xv0, w23.y);
                fma2(acc[1][active(IC, 3)], xv1, w23.y);
            }
            {
                ulonglong2 w45 = wp[2];
                fma2(acc[0][active(IC, 4)], xv0, w45.x);
                fma2(acc[1][active(IC, 4)], xv1, w45.x);
                fma2(acc[0][active(IC, 5)], xv0, w45.y);
                fma2(acc[1][active(IC, 5)], xv1, w45.y);
            }
            {
                ulonglong2 w67 = wp[3];
                fma2(acc[0][active(IC, 6)], xv0, w67.x);
                fma2(acc[1][active(IC, 6)], xv1, w67.x);
                fma2(acc[0][active(IC, 7)], xv0, w67.y);
                fma2(acc[1][active(IC, 7)], xv1, w67.y);
            }
            {
                ulonglong2 w89 = wp[4];
                fma2(acc[0][active(IC, 8)], xv0, w89.x);
                fma2(acc[1][active(IC, 8)], xv1, w89.x);
                fma2(acc[0][active(IC, 9)], xv0, w89.y);
                fma2(acc[1][active(IC, 9)], xv1, w89.y);
            }
        }
    }
}

__global__ __launch_bounds__(NTHREADS, 2)
void conv_c3_kernel(const float* __restrict__ x,
                    const float* __restrict__ W,
                    const float* __restrict__ b,
                    float* __restrict__ out)
{
    extern __shared__ float smem[];
    float* s_in = smem;                                   // 6*28*72 = 12096 floats
    float* s_w  = smem + NIC * IN_ROWS * IN_WS;           // 6*25*20 = 3000 floats
    float* s_b  = s_w + NIC * 25 * 2 * NACT;              // 16 floats

    const int tid  = threadIdx.x;
    const int lane = tid & 31;
    const int warp = tid >> 5;
    const int n    = blockIdx.z;
    const int by0  = blockIdx.y * TILE_H;
    const int bx0  = blockIdx.x * TILE_W;

    // ---- Load input tile (coalesced LDG, interleaved STS) ----
    const float* xin = x + (size_t)n * NIC * IH * IW;
    #pragma unroll 1
    for (int rowi = warp; rowi < NIC * IN_ROWS; rowi += NTHREADS / 32) {
        int ic = rowi / IN_ROWS;
        int r  = rowi % IN_ROWS;
        int gy = by0 + r;
        const float* src = xin + ((size_t)ic * IH + gy) * IW;
        float* dstrow = s_in + (ic * IN_ROWS + r) * IN_WS;
        #pragma unroll
        for (int cc = 0; cc < 3; cc++) {
            int c = lane + cc * 32;
            if (c < 68) {
                int gx = bx0 + c;
                float v = 0.0f;
                if (gy < IH && gx < IW) v = __ldg(src + gx);
                if (c < 36)  dstrow[2 * c] = v;
                if (c >= 32) dstrow[2 * (c - 32) + 1] = v;
            }
        }
    }

    // ---- Load packed active weights, duplicated as (w,w) pairs ----
    #pragma unroll 1
    for (int idx = tid; idx < NIC * 25 * NACT; idx += NTHREADS) {
        int ic   = idx / (25 * NACT);
        int rem  = idx % (25 * NACT);
        int k    = rem / NACT;
        int slot = rem % NACT;
        int oc   = active(ic, slot);
        float wv = W[oc * (NIC * 25) + ic * 25 + k];
        s_w[(ic * 25 + k) * (2 * NACT) + 2 * slot]     = wv;
        s_w[(ic * 25 + k) * (2 * NACT) + 2 * slot + 1] = wv;
    }
    if (tid < NOC) s_b[tid] = b[tid];
    __syncthreads();

    // ---- Compute ----
    const int tx   = lane;           // owns output cols bx0+tx and bx0+tx+32
    const int row0 = warp * RPT;     // owns output rows by0+row0 .. +RPT-1

    // Init accumulators with (bias, bias) — epilogue add comes for free.
    ull acc[RPT][NOC];
    #pragma unroll
    for (int o = 0; o < NOC; o++) {
        float bo = s_b[o];
        unsigned u = __float_as_uint(bo);
        ull bb = ((ull)u << 32) | (ull)u;
        #pragma unroll
        for (int r = 0; r < RPT; r++) acc[r][o] = bb;
    }

    conv_ic<0>(s_in, s_w, acc, row0, tx);
    conv_ic<1>(s_in, s_w, acc, row0, tx);
    conv_ic<2>(s_in, s_w, acc, row0, tx);
    conv_ic<3>(s_in, s_w, acc, row0, tx);
    conv_ic<4>(s_in, s_w, acc, row0, tx);
    conv_ic<5>(s_in, s_w, acc, row0, tx);

    // ---- Epilogue: store ----
    const int x0 = bx0 + tx;
    const int x1 = x0 + 32;
    #pragma unroll
    for (int r = 0; r < RPT; r++) {
        int y = by0 + row0 + r;
        if (y >= OH) continue;
        #pragma unroll
        for (int oc = 0; oc < NOC; oc++) {
            float lo = __uint_as_float((unsigned)(acc[r][oc] & 0xffffffffull));
            float hi = __uint_as_float((unsigned)(acc[r][oc] >> 32));
            size_t base = ((size_t)(n * NOC + oc) * OH + y) * OW;
            if (x0 < OW) out[base + x0] = lo;
            if (x1 < OW) out[base + x1] = hi;
        }
    }
}

extern "C" void kernel_launch(void* const* d_in, const int* in_sizes, int n_in,
                              void* d_out, int out_size) {
    const float* x = (const float*)d_in[0];
    const float* W = (const float*)d_in[1];
    const float* b = (const float*)d_in[2];
    float* out = (float*)d_out;

    const int smem_bytes = (NIC * IN_ROWS * IN_WS + NIC * 25 * 2 * NACT + NOC) * 4;
    cudaFuncSetAttribute(conv_c3_kernel,
                         cudaFuncAttributeMaxDynamicSharedMemorySize, smem_bytes);

    const int n_batch = in_sizes[0] / (NIC * IH * IW);   // 64
    dim3 grid((OW + TILE_W - 1) / TILE_W,    // 8
              (OH + TILE_H - 1) / TILE_H,    // 22
              n_batch);                       // 64
    conv_c3_kernel<<<grid, NTHREADS, smem_bytes>>>(x, W, b, out);
}